// round 15
// baseline (speedup 1.0000x reference)
#include <cuda_runtime.h>
#include <cuda_bf16.h>
#include <stdint.h>

// ---------------- problem constants ----------------
#define BATCH   64
#define HDIM    512
#define WDIM    512
#define NPIX    (HDIM*WDIM)          // 262144
#define NWORDS  (NPIX/32)
#define NIMG    (2*BATCH)            // 128
#define NPTS    1000
#define NPTSP   1008                 // padded stride (mult of 8 + sentinels)
#define CANDCAP 4096
#define PARTS   4
#define FUSEDBLOCKS (NIMG*64)        // 8192
#define HDBLOCKS (BATCH*2*PARTS)     // 512
#define BNDCAP  512
// integer acceptance threshold: accept iff rnd >= KTH9 (== (rnd>>9) >= KTH).
#define KTH     8327961u
#define KTH9    4263916032u          // KTH << 9

typedef unsigned long long u64;

// packed f32x2 FMA (Blackwell): halves fma-pipe instruction count.
#define FMA2(out, a, b, c) \
    asm("fma.rn.f32x2 %0, %1, %2, %3;" : "=l"(out) : "l"(a), "l"(b), "l"(c))

__device__ __forceinline__ u64 pack2(float x) {
    uint32_t b = __float_as_uint(x);
    return ((u64)b << 32) | (u64)b;
}
__device__ __forceinline__ float lo2(u64 v) { return __uint_as_float((uint32_t)v); }
__device__ __forceinline__ float hi2(u64 v) { return __uint_as_float((uint32_t)(v >> 32)); }

// ---------------- device scratch (zero-init; self-cleaning) ----------------
__device__ uint32_t g_validbits[NIMG*NWORDS];
__device__ uint32_t g_nvalid[NIMG];
__device__ uint32_t g_candcnt[NIMG];
__device__ uint32_t g_imgdone[NIMG];
__device__ uint32_t g_ready[NIMG];
__device__ unsigned long long g_cand[(size_t)NIMG*CANDCAP];
__device__ float    g_lx[NIMG*NPTSP];
__device__ float    g_ly[NIMG*NPTSP];
__device__ float    g_q [NIMG*NPTSP];
__device__ int      g_np[NIMG];
__device__ unsigned int g_hdbits[BATCH];
__device__ unsigned int g_done;

// ---------------- threefry2x32 (JAX partitionable semantics) ----------------
__device__ __forceinline__ uint32_t rotl32(uint32_t x, int r) {
    return __funnelshift_l(x, x, r);
}
__device__ __forceinline__ void threefry2x32(uint32_t k0, uint32_t k1,
                                             uint32_t x0, uint32_t x1,
                                             uint32_t& o0, uint32_t& o1) {
    uint32_t ks2 = k0 ^ k1 ^ 0x1BD11BDAu;
    x0 += k0; x1 += k1;
#define TF_RND(r) { x0 += x1; x1 = rotl32(x1, r); x1 ^= x0; }
    TF_RND(13) TF_RND(15) TF_RND(26) TF_RND(6)   x0 += k1;  x1 += ks2 + 1u;
    TF_RND(17) TF_RND(29) TF_RND(16) TF_RND(24)  x0 += ks2; x1 += k0  + 2u;
    TF_RND(13) TF_RND(15) TF_RND(26) TF_RND(6)   x0 += k0;  x1 += k1  + 3u;
    TF_RND(17) TF_RND(29) TF_RND(16) TF_RND(24)  x0 += k1;  x1 += ks2 + 4u;
    TF_RND(13) TF_RND(15) TF_RND(26) TF_RND(6)   x0 += ks2; x1 += k0  + 5u;
#undef TF_RND
    o0 = x0; o1 = x1;
}
// pre-added variant: x1 = k1 + counter already added by caller.
__device__ __forceinline__ uint32_t threefry_xor(uint32_t k0, uint32_t k1,
                                                 uint32_t ks2, uint32_t x1) {
    uint32_t x0 = k0;
#define TF_RND(r) { x0 += x1; x1 = rotl32(x1, r); x1 ^= x0; }
    TF_RND(13) TF_RND(15) TF_RND(26) TF_RND(6)   x0 += k1;  x1 += ks2 + 1u;
    TF_RND(17) TF_RND(29) TF_RND(16) TF_RND(24)  x0 += ks2; x1 += k0  + 2u;
    TF_RND(13) TF_RND(15) TF_RND(26) TF_RND(6)   x0 += k0;  x1 += k1  + 3u;
    TF_RND(17) TF_RND(29) TF_RND(16) TF_RND(24)  x0 += k1;  x1 += ks2 + 4u;
    TF_RND(13) TF_RND(15) TF_RND(26) TF_RND(6)   x0 += ks2; x1 += k0  + 5u;
#undef TF_RND
    return x0 ^ x1;
}
__device__ __forceinline__ float bits_to_uniform(uint32_t bits) {
    return __uint_as_float((bits >> 9) | 0x3F800000u) - 1.0f;
}
// partitionable split(key(1),128): key_b = threefry((0,1), (0,b))
__device__ __forceinline__ void image_key(int b, uint32_t& k0, uint32_t& k1) {
    threefry2x32(0u, 1u, 0u, (uint32_t)b, k0, k1);
}

__device__ __forceinline__ void emit_point(int b, unsigned int pos, uint32_t idx) {
    float x = (float)(idx >> 9), y = (float)(idx & 511);
    g_lx[b * NPTSP + pos] = x;
    g_ly[b * NPTSP + pos] = y;
    g_q [b * NPTSP + pos] = x * x + y * y;
}

// ---------------- selection (runs in the last-finishing block of an image) ---
__device__ __noinline__ void select_image(int b, uint32_t* hist,
                                          unsigned long long* bnd) {
    __shared__ uint32_t tsum[256];
    __shared__ uint32_t esuf[256];
    __shared__ unsigned int s_rc, s_emit, s_bcnt, s_C, s_G;
    int tid = threadIdx.x;
    unsigned int cnt = g_candcnt[b]; if (cnt > CANDCAP) cnt = CANDCAP;
    unsigned int nv  = g_nvalid[b];
    unsigned int needed = (nv < (unsigned)NPTS) ? nv : (unsigned)NPTS;
    bool rescued = false;
    if (cnt < needed) {
        // RESCUE: adaptive tau; statistically never taken.
        if (tid == 0) s_rc = 0u;
        __syncthreads();
        uint32_t k0, k1; image_key(b, k0, k1);
        uint32_t tau = 0u;
        if (nv > 2500u)
            tau = __float_as_uint(2.0f + (1.0f - 2048.0f / (float)nv));
        int lane = tid & 31;
        for (int i = tid; i < NPIX; i += 256) {
            uint32_t vw = g_validbits[b * NWORDS + (i >> 5)];
            bool v = (vw >> lane) & 1u;
            uint32_t o0, o1;
            threefry2x32(k0, k1, 0u, (uint32_t)i, o0, o1);
            uint32_t sb = __float_as_uint(2.0f + bits_to_uniform(o0 ^ o1));
            bool acc = v && (sb >= tau);
            unsigned int amask = __ballot_sync(0xffffffffu, acc);
            if (amask) {
                int leader = __ffs(amask) - 1;
                uint32_t base = 0;
                if (lane == leader) base = atomicAdd(&s_rc, (uint32_t)__popc(amask));
                base = __shfl_sync(0xffffffffu, base, leader);
                if (acc) {
                    uint32_t pos = base + __popc(amask & ((1u << lane) - 1u));
                    if (pos < CANDCAP)
                        g_cand[(size_t)b * CANDCAP + pos] =
                            (((unsigned long long)sb) << 32)
                          | (unsigned long long)(~(uint32_t)i);
                }
            }
        }
        __syncthreads();
        cnt = s_rc; if (cnt > CANDCAP) cnt = CANDCAP;
        rescued = true;
    }
    if (needed > cnt) needed = cnt;

    int npts;
    if (cnt == 0u) {
        npts = 1;
        if (tid == 0) {
            g_lx[b * NPTSP] = 256.0f;
            g_ly[b * NPTSP] = 256.0f;
            g_q [b * NPTSP] = 131072.0f;
        }
    } else if (cnt <= needed) {
        npts = (int)cnt;                      // take everything
        for (unsigned int i = tid; i < cnt; i += 256)
            emit_point(b, i, ~(uint32_t)g_cand[(size_t)b * CANDCAP + i]);
    } else {
        npts = (int)needed;
        const uint32_t SB = rescued ? 0x40000000u : 0x403F0000u;
        const int      SH = rescued ? 12 : 4;
        for (int k = tid; k < 4096; k += 256) hist[k] = 0u;
        if (tid == 0) { s_emit = 0u; s_bcnt = 0u; }
        __syncthreads();
        for (unsigned int i = tid; i < cnt; i += 256) {
            uint32_t sb = (uint32_t)(g_cand[(size_t)b * CANDCAP + i] >> 32);
            int bin = (int)((sb - SB) >> SH); if (bin > 4095) bin = 4095;
            atomicAdd(&hist[bin], 1u);
        }
        __syncthreads();
        {   // suffix scan for cutoff bin C, G = count above C
            uint32_t ls = 0;
            int base = tid * 16;
            for (int k = 0; k < 16; k++) ls += hist[base + k];
            tsum[tid] = ls;
        }
        __syncthreads();
        if (tid < 32) {
            uint32_t g = 0;
            for (int k = 0; k < 8; k++) g += tsum[tid * 8 + k];
            uint32_t sfx = g;
            for (int off = 1; off < 32; off <<= 1) {
                uint32_t o = __shfl_down_sync(0xffffffffu, sfx, off);
                if (tid + off < 32) sfx += o;
            }
            uint32_t cum = sfx - g;
            for (int k = 7; k >= 0; k--) {
                esuf[tid * 8 + k] = cum;
                cum += tsum[tid * 8 + k];
            }
        }
        __syncthreads();
        {
            uint32_t sa = esuf[tid];
            if (sa < needed && sa + tsum[tid] >= needed) {
                uint32_t cum = sa;
                for (int bin = tid * 16 + 15; ; bin--) {
                    uint32_t h = hist[bin];
                    if (cum + h >= needed) { s_C = (unsigned)bin; s_G = cum; break; }
                    cum += h;
                }
            }
        }
        __syncthreads();
        unsigned int C = s_C, G = s_G;
        for (unsigned int i = tid; i < cnt; i += 256) {
            unsigned long long key = g_cand[(size_t)b * CANDCAP + i];
            uint32_t sb = (uint32_t)(key >> 32);
            int bin = (int)((sb - SB) >> SH); if (bin > 4095) bin = 4095;
            if (bin > (int)C) {
                unsigned int pos = atomicAdd(&s_emit, 1u);
                emit_point(b, pos, ~(uint32_t)key);
            } else if (bin == (int)C) {
                unsigned int p = atomicAdd(&s_bcnt, 1u);
                if (p < BNDCAP) bnd[p] = key;
            }
        }
        __syncthreads();
        unsigned int bcnt = s_bcnt; if (bcnt > BNDCAP) bcnt = BNDCAP;
        int n2 = 2; while (n2 < (int)bcnt) n2 <<= 1;
        for (int i = (int)bcnt + tid; i < n2; i += 256) bnd[i] = 0ull;
        __syncthreads();
        for (int k = 2; k <= n2; k <<= 1) {           // sort desc by full key
            for (int j = k >> 1; j > 0; j >>= 1) {
                for (int i = tid; i < n2; i += 256) {
                    int ixj = i ^ j;
                    if (ixj > i) {
                        unsigned long long a = bnd[i], bb = bnd[ixj];
                        if ((a < bb) == ((i & k) == 0)) { bnd[i] = bb; bnd[ixj] = a; }
                    }
                }
                __syncthreads();
            }
        }
        unsigned int take = needed - G; if (take > bcnt) take = bcnt;
        for (unsigned int j = tid; j < take; j += 256)
            emit_point(b, G + j, ~(uint32_t)bnd[j]);
    }
    __syncthreads();
    int pad = (npts + 7) & ~7;                       // sentinels
    for (int j = npts + tid; j < pad; j += 256) {
        g_lx[b * NPTSP + j] = 0.0f;
        g_ly[b * NPTSP + j] = 0.0f;
        g_q [b * NPTSP + j] = 3.0e38f;
    }
    __syncthreads();                                 // all emits done
    if (tid == 0) {
        g_np[b] = npts;
        g_candcnt[b] = 0u;     // self-clean for graph replay
        g_nvalid[b]  = 0u;
        g_imgdone[b] = 0u;
        __threadfence();
        atomicExch(&g_ready[b], 1u);   // release: hd blocks may proceed
    }
}

// ================= merged kernel: fused blocks then hd blocks ================
__global__ void __launch_bounds__(256) k_all(const float* __restrict__ pred,
                                             const float* __restrict__ target,
                                             float* __restrict__ out) {
    __shared__ __align__(16) unsigned char s_raw[20640];
    __shared__ unsigned int blkcnt;
    __shared__ uint32_t skey[2];
    __shared__ uint32_t s_tb;
    __shared__ int s_flag;
    __shared__ float red[8];
    int bxg = blockIdx.x;
    int tid = threadIdx.x;

    if (bxg < FUSEDBLOCKS) {
        // ---------------- fused: Sobel(+sigmoid) + threefry + accept ----------
        float (*s)[514] = reinterpret_cast<float(*)[514]>(s_raw);
        int b   = bxg >> 6;
        int r0  = (bxg & 63) << 3;
        if (tid == 0) {
            blkcnt = 0u;
            // exact bits threshold T: z >= T  <=>  sqrtf(z) > 0.1f
            double mid = (double)0.1f + 3.7252902984619140625e-9;
            double T = mid * mid;
            float t1 = (float)T;
            uint32_t tb = __float_as_uint(t1);
            if ((double)t1 < T) tb++;
            s_tb = tb;
        }
        bool isPred = (b < BATCH);
        const float* src = isPred ? (pred + (size_t)b * NPIX)
                                  : (target + (size_t)(b - BATCH) * NPIX);
        for (int idx = tid; idx < 1280; idx += 256) {
            int lr = idx >> 7;
            int c4 = (idx & 127) << 2;
            int gr = r0 + lr - 1;
            float4 v;
            if (gr >= 0 && gr < HDIM) {
                v = *reinterpret_cast<const float4*>(src + ((size_t)gr << 9) + c4);
                if (isPred) {
                    v.x = __fdividef(1.0f, 1.0f + __expf(-v.x));
                    v.y = __fdividef(1.0f, 1.0f + __expf(-v.y));
                    v.z = __fdividef(1.0f, 1.0f + __expf(-v.z));
                    v.w = __fdividef(1.0f, 1.0f + __expf(-v.w));
                }
            } else v = make_float4(0.f, 0.f, 0.f, 0.f);
            s[lr][1 + c4] = v.x; s[lr][2 + c4] = v.y;
            s[lr][3 + c4] = v.z; s[lr][4 + c4] = v.w;
            if (c4 == 0) { s[lr][0] = 0.f; s[lr][513] = 0.f; }
        }
        if (tid < 32) {
            uint32_t a, c;
            image_key(b, a, c);
            if (tid == 0) { skey[0] = a; skey[1] = c; }
        }
        __syncthreads();
        const uint32_t k0 = skey[0], k1 = skey[1], tb = s_tb;
        const uint32_t ks2 = k0 ^ k1 ^ 0x1BD11BDAu;
        const int w = tid >> 5, lane = tid & 31;
        const int sc0   = w * 32 + lane + 1;
        const uint32_t ibase = (uint32_t)((r0 << 9) + w * 32 + lane);
        const uint32_t k1i   = k1 + ibase;
        const int vb0   = b * NWORDS + r0 * 16 + w;
        unsigned int myc = 0;
#pragma unroll
        for (int h = 0; h < 2; h++) {
            const int sc = sc0 + h * 256;
            const uint32_t k1h = k1i + 256u * (uint32_t)h;
            float AL = s[0][sc-1], AM = s[0][sc], AR = s[0][sc+1];
            float BL = s[1][sc-1], BM = s[1][sc], BR = s[1][sc+1];
#pragma unroll
            for (int row8 = 0; row8 < 8; row8++) {
                float CL = s[row8+2][sc-1], CM = s[row8+2][sc], CR = s[row8+2][sc+1];
                float gx = (AR - AL) + 2.0f * (BR - BL) + (CR - CL);
                float gy = (CL + 2.0f * CM + CR) - (AL + 2.0f * AM + AR);
                float z  = gx * gx + gy * gy + 1e-8f;
                bool v = __float_as_uint(z) >= tb;   // == (sqrtf(z) > 0.1f)
                unsigned int word = __ballot_sync(0xffffffffu, v);
                if (lane == 0) {
                    g_validbits[vb0 + row8 * 16 + h * 8] = word;
                    myc += __popc(word);
                }
                uint32_t rnd = threefry_xor(k0, k1, ks2, k1h + 512u * (uint32_t)row8);
                unsigned int amask = word & __ballot_sync(0xffffffffu, rnd >= KTH9);
                if (amask) {
                    bool acc = (amask >> lane) & 1u;
                    int leader = __ffs(amask) - 1;
                    uint32_t base = 0;
                    if (lane == leader)
                        base = atomicAdd(&g_candcnt[b], (uint32_t)__popc(amask));
                    base = __shfl_sync(0xffffffffu, base, leader);
                    if (acc) {
                        uint32_t pos = base + __popc(amask & ((1u << lane) - 1u));
                        if (pos < CANDCAP) {
                            uint32_t kk = rnd >> 9;
                            float uu = __uint_as_float(kk | 0x3F800000u) - 1.0f;
                            uint32_t sb = __float_as_uint(2.0f + uu);
                            uint32_t i = ibase + 256u * (uint32_t)h
                                       + 512u * (uint32_t)row8;
                            g_cand[(size_t)b * CANDCAP + pos] =
                                (((unsigned long long)sb) << 32)
                              | (unsigned long long)(~i);
                        }
                    }
                }
                AL = BL; AM = BM; AR = BR;
                BL = CL; BM = CM; BR = CR;
            }
        }
        if (lane == 0 && myc) atomicAdd(&blkcnt, myc);
        __syncthreads();
        if (tid == 0 && blkcnt) atomicAdd(&g_nvalid[b], blkcnt);
        __threadfence();
        __syncthreads();
        if (tid == 0) {
            unsigned int old = atomicAdd(&g_imgdone[b], 1u);
            s_flag = (old == 63u);
        }
        __syncthreads();
        if (s_flag) {
            __threadfence();
            uint32_t* hist = reinterpret_cast<uint32_t*>(s_raw);
            unsigned long long* bnd =
                reinterpret_cast<unsigned long long*>(s_raw + 16384);
            select_image(b, hist, bnd);
        }
    } else {
        // ---------------- hd: one (image, dir, part); overlaps fused tail -----
        int blk  = bxg - FUSEDBLOCKS;
        int b    = blk >> 3;
        int dir  = (blk >> 2) & 1;
        int part = blk & 3;
        int qimg = dir ? (BATCH + b) : b;
        int rimg = dir ? b : (BATCH + b);
        if (tid == 0) {
            s_flag = 0;
            while (atomicAdd(&g_ready[b], 0u) == 0u) __nanosleep(128);
            while (atomicAdd(&g_ready[BATCH + b], 0u) == 0u) __nanosleep(128);
            __threadfence();              // acquire
        }
        __syncthreads();
        float* rx = reinterpret_cast<float*>(s_raw);
        float* ry = reinterpret_cast<float*>(s_raw + 4096);
        float* rq = reinterpret_cast<float*>(s_raw + 8192);
        int nq  = g_np[qimg];
        int nr8 = (g_np[rimg] + 7) & ~7;
        for (int i4 = tid * 4; i4 < nr8; i4 += 1024) {
            *reinterpret_cast<float4*>(&rx[i4]) =
                *reinterpret_cast<const float4*>(&g_lx[rimg * NPTSP + i4]);
            *reinterpret_cast<float4*>(&ry[i4]) =
                *reinterpret_cast<const float4*>(&g_ly[rimg * NPTSP + i4]);
            *reinterpret_cast<float4*>(&rq[i4]) =
                *reinterpret_cast<const float4*>(&g_q [rimg * NPTSP + i4]);
        }
        __syncthreads();
        int ch = (nq + PARTS - 1) / PARTS;       // <= 250
        int i0 = part * ch;
        int i1 = (i0 + ch < nq) ? (i0 + ch) : nq;
        int iq = i0 + tid;
        bool act = iq < i1;
        int rd = act ? iq : 0;
        float x = g_lx[qimg * NPTSP + rd], y = g_ly[qimg * NPTSP + rd];
        u64 nx2 = pack2(-2.0f * x), ny2 = pack2(-2.0f * y);
        float xx = fmaf(x, x, y * y);
        float m0 = 3.4e38f, m1 = 3.4e38f;
        for (int j = 0; j < nr8; j += 8) {
            const ulonglong2 tx0 = *reinterpret_cast<const ulonglong2*>(&rx[j]);
            const ulonglong2 ty0 = *reinterpret_cast<const ulonglong2*>(&ry[j]);
            const ulonglong2 tq0 = *reinterpret_cast<const ulonglong2*>(&rq[j]);
            const ulonglong2 tx1 = *reinterpret_cast<const ulonglong2*>(&rx[j + 4]);
            const ulonglong2 ty1 = *reinterpret_cast<const ulonglong2*>(&ry[j + 4]);
            const ulonglong2 tq1 = *reinterpret_cast<const ulonglong2*>(&rq[j + 4]);
            u64 i0v, i1v, i2v, i3v, d0, d1, d2, d3;
            FMA2(i0v, ty0.x, ny2, tq0.x);  FMA2(d0, tx0.x, nx2, i0v);
            FMA2(i1v, ty0.y, ny2, tq0.y);  FMA2(d1, tx0.y, nx2, i1v);
            FMA2(i2v, ty1.x, ny2, tq1.x);  FMA2(d2, tx1.x, nx2, i2v);
            FMA2(i3v, ty1.y, ny2, tq1.y);  FMA2(d3, tx1.y, nx2, i3v);
            m0 = fminf(m0, fminf(lo2(d0), hi2(d0)));
            m1 = fminf(m1, fminf(lo2(d1), hi2(d1)));
            m0 = fminf(m0, fminf(lo2(d2), hi2(d2)));
            m1 = fminf(m1, fminf(lo2(d3), hi2(d3)));
        }
        float lmax = 0.0f;
        if (act) lmax = fmaxf(fminf(m0, m1) + xx, 0.0f);
        for (int off = 16; off; off >>= 1)
            lmax = fmaxf(lmax, __shfl_down_sync(0xffffffffu, lmax, off));
        if ((tid & 31) == 0) red[tid >> 5] = lmax;
        __syncthreads();
        if (tid == 0) {
            float vv = red[0];
#pragma unroll
            for (int r = 1; r < 8; r++) vv = fmaxf(vv, red[r]);
            atomicMax(&g_hdbits[b], __float_as_uint(vv));
            __threadfence();
            unsigned int old = atomicAdd(&g_done, 1u);
            s_flag = (old == HDBLOCKS - 1);
        }
        __syncthreads();
        if (s_flag && tid == 0) {
            __threadfence();
            float diag = sqrtf((float)(HDIM * HDIM + WDIM * WDIM));
            float ssum = 0.0f;
            for (int i = 0; i < BATCH; i++) {
                float hd = sqrtf(__uint_as_float(g_hdbits[i])) / diag;
                ssum += fminf(fmaxf(hd, 0.0f), 0.1f);
                g_hdbits[i] = 0u;                       // self-clean
            }
            out[0] = ssum / (float)BATCH;
            g_done = 0u;                                // self-clean
            for (int i = 0; i < NIMG; i++) g_ready[i] = 0u;
        }
    }
}

// ---------------- launch ----------------
extern "C" void kernel_launch(void* const* d_in, const int* in_sizes, int n_in,
                              void* d_out, int out_size) {
    const float* pred   = (const float*)d_in[0];
    const float* target = (const float*)d_in[1];
    float* out = (float*)d_out;

    k_all<<<FUSEDBLOCKS + HDBLOCKS, 256>>>(pred, target, out);
}

// round 16
// speedup vs baseline: 1.4297x; 1.4297x over previous
#include <cuda_runtime.h>
#include <cuda_bf16.h>
#include <stdint.h>

// ---------------- problem constants ----------------
#define BATCH   64
#define HDIM    512
#define WDIM    512
#define NPIX    (HDIM*WDIM)          // 262144
#define NWORDS  (NPIX/32)
#define NIMG    (2*BATCH)            // 128
#define NPTS    1000
#define NPTSP   1008                 // padded stride (mult of 8 + sentinels)
#define CANDCAP 4096
#define PARTS   4
#define HDBLOCKS (BATCH*2*PARTS)     // 512
#define BNDCAP  512
// integer acceptance threshold: accept iff rnd >= KTH9 (== (rnd>>9) >= KTH).
#define KTH     8327961u
#define KTH9    4263916032u          // KTH << 9

typedef unsigned long long u64;

// packed f32x2 FMA (Blackwell): halves fma-pipe instruction count.
#define FMA2(out, a, b, c) \
    asm("fma.rn.f32x2 %0, %1, %2, %3;" : "=l"(out) : "l"(a), "l"(b), "l"(c))

__device__ __forceinline__ u64 pack2(float x) {
    uint32_t b = __float_as_uint(x);
    return ((u64)b << 32) | (u64)b;
}
__device__ __forceinline__ float lo2(u64 v) { return __uint_as_float((uint32_t)v); }
__device__ __forceinline__ float hi2(u64 v) { return __uint_as_float((uint32_t)(v >> 32)); }

// ---------------- device scratch (zero-init; self-cleaning) ----------------
__device__ uint32_t g_validbits[NIMG*NWORDS];
__device__ uint32_t g_nvalid[NIMG];
__device__ uint32_t g_candcnt[NIMG];
__device__ uint32_t g_imgdone[NIMG];
__device__ unsigned long long g_cand[(size_t)NIMG*CANDCAP];
__device__ float    g_lx[NIMG*NPTSP];
__device__ float    g_ly[NIMG*NPTSP];
__device__ float    g_q [NIMG*NPTSP];
__device__ int      g_np[NIMG];
__device__ unsigned int g_hdbits[BATCH];
__device__ unsigned int g_done;

// ---------------- threefry2x32 (JAX partitionable semantics) ----------------
__device__ __forceinline__ uint32_t rotl32(uint32_t x, int r) {
    return __funnelshift_l(x, x, r);
}
__device__ __forceinline__ void threefry2x32(uint32_t k0, uint32_t k1,
                                             uint32_t x0, uint32_t x1,
                                             uint32_t& o0, uint32_t& o1) {
    uint32_t ks2 = k0 ^ k1 ^ 0x1BD11BDAu;
    x0 += k0; x1 += k1;
#define TF_RND(r) { x0 += x1; x1 = rotl32(x1, r); x1 ^= x0; }
    TF_RND(13) TF_RND(15) TF_RND(26) TF_RND(6)   x0 += k1;  x1 += ks2 + 1u;
    TF_RND(17) TF_RND(29) TF_RND(16) TF_RND(24)  x0 += ks2; x1 += k0  + 2u;
    TF_RND(13) TF_RND(15) TF_RND(26) TF_RND(6)   x0 += k0;  x1 += k1  + 3u;
    TF_RND(17) TF_RND(29) TF_RND(16) TF_RND(24)  x0 += k1;  x1 += ks2 + 4u;
    TF_RND(13) TF_RND(15) TF_RND(26) TF_RND(6)   x0 += ks2; x1 += k0  + 5u;
#undef TF_RND
    o0 = x0; o1 = x1;
}
// pre-added variant: x1 = k1 + counter already added by caller.
__device__ __forceinline__ uint32_t threefry_xor(uint32_t k0, uint32_t k1,
                                                 uint32_t ks2, uint32_t x1) {
    uint32_t x0 = k0;
#define TF_RND(r) { x0 += x1; x1 = rotl32(x1, r); x1 ^= x0; }
    TF_RND(13) TF_RND(15) TF_RND(26) TF_RND(6)   x0 += k1;  x1 += ks2 + 1u;
    TF_RND(17) TF_RND(29) TF_RND(16) TF_RND(24)  x0 += ks2; x1 += k0  + 2u;
    TF_RND(13) TF_RND(15) TF_RND(26) TF_RND(6)   x0 += k0;  x1 += k1  + 3u;
    TF_RND(17) TF_RND(29) TF_RND(16) TF_RND(24)  x0 += k1;  x1 += ks2 + 4u;
    TF_RND(13) TF_RND(15) TF_RND(26) TF_RND(6)   x0 += ks2; x1 += k0  + 5u;
#undef TF_RND
    return x0 ^ x1;
}
__device__ __forceinline__ float bits_to_uniform(uint32_t bits) {
    return __uint_as_float((bits >> 9) | 0x3F800000u) - 1.0f;
}
// partitionable split(key(1),128): key_b = threefry((0,1), (0,b))
__device__ __forceinline__ void image_key(int b, uint32_t& k0, uint32_t& k1) {
    threefry2x32(0u, 1u, 0u, (uint32_t)b, k0, k1);
}

__device__ __forceinline__ void emit_point(int b, unsigned int pos, uint32_t idx) {
    float x = (float)(idx >> 9), y = (float)(idx & 511);
    g_lx[b * NPTSP + pos] = x;
    g_ly[b * NPTSP + pos] = y;
    g_q [b * NPTSP + pos] = x * x + y * y;
}

// ---------------- selection (runs in the last-finishing block of an image) ---
__device__ __noinline__ void select_image(int b, uint32_t* hist,
                                          unsigned long long* bnd) {
    __shared__ uint32_t tsum[256];
    __shared__ uint32_t esuf[256];
    __shared__ unsigned int s_rc, s_emit, s_bcnt, s_C, s_G;
    int tid = threadIdx.x;
    unsigned int cnt = g_candcnt[b]; if (cnt > CANDCAP) cnt = CANDCAP;
    unsigned int nv  = g_nvalid[b];
    unsigned int needed = (nv < (unsigned)NPTS) ? nv : (unsigned)NPTS;
    bool rescued = false;
    if (cnt < needed) {
        // RESCUE: adaptive tau; statistically never taken.
        if (tid == 0) s_rc = 0u;
        __syncthreads();
        uint32_t k0, k1; image_key(b, k0, k1);
        uint32_t tau = 0u;
        if (nv > 2500u)
            tau = __float_as_uint(2.0f + (1.0f - 2048.0f / (float)nv));
        int lane = tid & 31;
        for (int i = tid; i < NPIX; i += 256) {
            uint32_t vw = g_validbits[b * NWORDS + (i >> 5)];
            bool v = (vw >> lane) & 1u;
            uint32_t o0, o1;
            threefry2x32(k0, k1, 0u, (uint32_t)i, o0, o1);
            uint32_t sb = __float_as_uint(2.0f + bits_to_uniform(o0 ^ o1));
            bool acc = v && (sb >= tau);
            unsigned int amask = __ballot_sync(0xffffffffu, acc);
            if (amask) {
                int leader = __ffs(amask) - 1;
                uint32_t base = 0;
                if (lane == leader) base = atomicAdd(&s_rc, (uint32_t)__popc(amask));
                base = __shfl_sync(0xffffffffu, base, leader);
                if (acc) {
                    uint32_t pos = base + __popc(amask & ((1u << lane) - 1u));
                    if (pos < CANDCAP)
                        g_cand[(size_t)b * CANDCAP + pos] =
                            (((unsigned long long)sb) << 32)
                          | (unsigned long long)(~(uint32_t)i);
                }
            }
        }
        __syncthreads();
        cnt = s_rc; if (cnt > CANDCAP) cnt = CANDCAP;
        rescued = true;
    }
    if (needed > cnt) needed = cnt;

    int npts;
    if (cnt == 0u) {
        npts = 1;
        if (tid == 0) {
            g_lx[b * NPTSP] = 256.0f;
            g_ly[b * NPTSP] = 256.0f;
            g_q [b * NPTSP] = 131072.0f;
        }
    } else if (cnt <= needed) {
        npts = (int)cnt;                      // take everything
        for (unsigned int i = tid; i < cnt; i += 256)
            emit_point(b, i, ~(uint32_t)g_cand[(size_t)b * CANDCAP + i]);
    } else {
        npts = (int)needed;
        const uint32_t SB = rescued ? 0x40000000u : 0x403F0000u;
        const int      SH = rescued ? 12 : 4;
        for (int k = tid; k < 4096; k += 256) hist[k] = 0u;
        if (tid == 0) { s_emit = 0u; s_bcnt = 0u; }
        __syncthreads();
        for (unsigned int i = tid; i < cnt; i += 256) {
            uint32_t sb = (uint32_t)(g_cand[(size_t)b * CANDCAP + i] >> 32);
            int bin = (int)((sb - SB) >> SH); if (bin > 4095) bin = 4095;
            atomicAdd(&hist[bin], 1u);
        }
        __syncthreads();
        {   // suffix scan for cutoff bin C, G = count above C
            uint32_t ls = 0;
            int base = tid * 16;
            for (int k = 0; k < 16; k++) ls += hist[base + k];
            tsum[tid] = ls;
        }
        __syncthreads();
        if (tid < 32) {
            uint32_t g = 0;
            for (int k = 0; k < 8; k++) g += tsum[tid * 8 + k];
            uint32_t sfx = g;
            for (int off = 1; off < 32; off <<= 1) {
                uint32_t o = __shfl_down_sync(0xffffffffu, sfx, off);
                if (tid + off < 32) sfx += o;
            }
            uint32_t cum = sfx - g;
            for (int k = 7; k >= 0; k--) {
                esuf[tid * 8 + k] = cum;
                cum += tsum[tid * 8 + k];
            }
        }
        __syncthreads();
        {
            uint32_t sa = esuf[tid];
            if (sa < needed && sa + tsum[tid] >= needed) {
                uint32_t cum = sa;
                for (int bin = tid * 16 + 15; ; bin--) {
                    uint32_t h = hist[bin];
                    if (cum + h >= needed) { s_C = (unsigned)bin; s_G = cum; break; }
                    cum += h;
                }
            }
        }
        __syncthreads();
        unsigned int C = s_C, G = s_G;
        for (unsigned int i = tid; i < cnt; i += 256) {
            unsigned long long key = g_cand[(size_t)b * CANDCAP + i];
            uint32_t sb = (uint32_t)(key >> 32);
            int bin = (int)((sb - SB) >> SH); if (bin > 4095) bin = 4095;
            if (bin > (int)C) {
                unsigned int pos = atomicAdd(&s_emit, 1u);
                emit_point(b, pos, ~(uint32_t)key);
            } else if (bin == (int)C) {
                unsigned int p = atomicAdd(&s_bcnt, 1u);
                if (p < BNDCAP) bnd[p] = key;
            }
        }
        __syncthreads();
        unsigned int bcnt = s_bcnt; if (bcnt > BNDCAP) bcnt = BNDCAP;
        int n2 = 2; while (n2 < (int)bcnt) n2 <<= 1;
        for (int i = (int)bcnt + tid; i < n2; i += 256) bnd[i] = 0ull;
        __syncthreads();
        for (int k = 2; k <= n2; k <<= 1) {           // sort desc by full key
            for (int j = k >> 1; j > 0; j >>= 1) {
                for (int i = tid; i < n2; i += 256) {
                    int ixj = i ^ j;
                    if (ixj > i) {
                        unsigned long long a = bnd[i], bb = bnd[ixj];
                        if ((a < bb) == ((i & k) == 0)) { bnd[i] = bb; bnd[ixj] = a; }
                    }
                }
                __syncthreads();
            }
        }
        unsigned int take = needed - G; if (take > bcnt) take = bcnt;
        for (unsigned int j = tid; j < take; j += 256)
            emit_point(b, G + j, ~(uint32_t)bnd[j]);
    }
    __syncthreads();
    int pad = (npts + 7) & ~7;                       // sentinels
    for (int j = npts + tid; j < pad; j += 256) {
        g_lx[b * NPTSP + j] = 0.0f;
        g_ly[b * NPTSP + j] = 0.0f;
        g_q [b * NPTSP + j] = 3.0e38f;
    }
    if (tid == 0) {
        g_np[b] = npts;
        g_candcnt[b] = 0u;     // self-clean for graph replay
        g_nvalid[b]  = 0u;
        g_imgdone[b] = 0u;
    }
}

// ---------------- k_fused: Sobel(+sigmoid) + threefry + accept + selection ---
__global__ void __launch_bounds__(256) k_fused(const float* __restrict__ pred,
                                               const float* __restrict__ target) {
    __shared__ __align__(16) unsigned char s_raw[20608];
    float (*s)[514] = reinterpret_cast<float(*)[514]>(s_raw);
    __shared__ unsigned int blkcnt;
    __shared__ uint32_t skey[2];
    __shared__ uint32_t s_tb;
    __shared__ int s_isLast;
    int bx  = blockIdx.x;
    int b   = bx >> 6;
    int r0  = (bx & 63) << 3;
    int tid = threadIdx.x;
    if (tid == 0) {
        blkcnt = 0u;
        // exact bits threshold T: z >= T  <=>  sqrtf(z) > 0.1f
        double mid = (double)0.1f + 3.7252902984619140625e-9;
        double T = mid * mid;
        float t1 = (float)T;
        uint32_t tb = __float_as_uint(t1);
        if ((double)t1 < T) tb++;
        s_tb = tb;
    }
    bool isPred = (b < BATCH);
    const float* src = isPred ? (pred + (size_t)b * NPIX)
                              : (target + (size_t)(b - BATCH) * NPIX);
    for (int idx = tid; idx < 1280; idx += 256) {
        int lr = idx >> 7;
        int c4 = (idx & 127) << 2;
        int gr = r0 + lr - 1;
        float4 v;
        if (gr >= 0 && gr < HDIM) {
            v = *reinterpret_cast<const float4*>(src + ((size_t)gr << 9) + c4);
            if (isPred) {
                v.x = __fdividef(1.0f, 1.0f + __expf(-v.x));
                v.y = __fdividef(1.0f, 1.0f + __expf(-v.y));
                v.z = __fdividef(1.0f, 1.0f + __expf(-v.z));
                v.w = __fdividef(1.0f, 1.0f + __expf(-v.w));
            }
        } else v = make_float4(0.f, 0.f, 0.f, 0.f);
        s[lr][1 + c4] = v.x; s[lr][2 + c4] = v.y;
        s[lr][3 + c4] = v.z; s[lr][4 + c4] = v.w;
        if (c4 == 0) { s[lr][0] = 0.f; s[lr][513] = 0.f; }
    }
    if (tid < 32) {
        uint32_t a, c;
        image_key(b, a, c);
        if (tid == 0) { skey[0] = a; skey[1] = c; }
    }
    __syncthreads();
    const uint32_t k0 = skey[0], k1 = skey[1], tb = s_tb;
    const uint32_t ks2 = k0 ^ k1 ^ 0x1BD11BDAu;
    const int w = tid >> 5, lane = tid & 31;
    const int sc0   = w * 32 + lane + 1;
    const uint32_t ibase = (uint32_t)((r0 << 9) + w * 32 + lane);
    const uint32_t k1i   = k1 + ibase;
    const int vb0   = b * NWORDS + r0 * 16 + w;
    unsigned int myc = 0;
    // half-major iteration with register sliding window: 3 LDS/pixel steady.
#pragma unroll
    for (int h = 0; h < 2; h++) {
        const int sc = sc0 + h * 256;
        const uint32_t k1h = k1i + 256u * (uint32_t)h;
        float AL = s[0][sc-1], AM = s[0][sc], AR = s[0][sc+1];
        float BL = s[1][sc-1], BM = s[1][sc], BR = s[1][sc+1];
#pragma unroll
        for (int row8 = 0; row8 < 8; row8++) {
            float CL = s[row8+2][sc-1], CM = s[row8+2][sc], CR = s[row8+2][sc+1];
            float gx = (AR - AL) + 2.0f * (BR - BL) + (CR - CL);
            float gy = (CL + 2.0f * CM + CR) - (AL + 2.0f * AM + AR);
            float z  = gx * gx + gy * gy + 1e-8f;
            bool v = __float_as_uint(z) >= tb;   // == (sqrtf(z) > 0.1f), exact
            unsigned int word = __ballot_sync(0xffffffffu, v);
            if (lane == 0) {
                g_validbits[vb0 + row8 * 16 + h * 8] = word;
                myc += __popc(word);
            }
            uint32_t rnd = threefry_xor(k0, k1, ks2, k1h + 512u * (uint32_t)row8);
            unsigned int amask = word & __ballot_sync(0xffffffffu, rnd >= KTH9);
            if (amask) {
                bool acc = (amask >> lane) & 1u;
                int leader = __ffs(amask) - 1;
                uint32_t base = 0;
                if (lane == leader)
                    base = atomicAdd(&g_candcnt[b], (uint32_t)__popc(amask));
                base = __shfl_sync(0xffffffffu, base, leader);
                if (acc) {
                    uint32_t pos = base + __popc(amask & ((1u << lane) - 1u));
                    if (pos < CANDCAP) {
                        uint32_t kk = rnd >> 9;
                        float uu = __uint_as_float(kk | 0x3F800000u) - 1.0f;
                        uint32_t sb = __float_as_uint(2.0f + uu);
                        uint32_t i = ibase + 256u * (uint32_t)h + 512u * (uint32_t)row8;
                        g_cand[(size_t)b * CANDCAP + pos] =
                            (((unsigned long long)sb) << 32) | (unsigned long long)(~i);
                    }
                }
            }
            AL = BL; AM = BM; AR = BR;
            BL = CL; BM = CM; BR = CR;
        }
    }
    if (lane == 0 && myc) atomicAdd(&blkcnt, myc);
    __syncthreads();
    if (tid == 0 && blkcnt) atomicAdd(&g_nvalid[b], blkcnt);
    // last-finishing block of this image runs selection
    __threadfence();
    __syncthreads();
    if (tid == 0) {
        unsigned int old = atomicAdd(&g_imgdone[b], 1u);
        s_isLast = (old == 63u);
    }
    __syncthreads();
    if (s_isLast) {
        __threadfence();
        uint32_t* hist = reinterpret_cast<uint32_t*>(s_raw);
        unsigned long long* bnd = reinterpret_cast<unsigned long long*>(s_raw + 16384);
        select_image(b, hist, bnd);
    }
}

// ---------------- k_hd_mean: 512 blocks = 64 img x 2 dir x 4 parts -----------
// FFMA2 packed pair-evals; 4 independent min-chains per query (latency fix).
__global__ void __launch_bounds__(128) k_hd_mean(float* __restrict__ out) {
    __shared__ __align__(16) float rx[NPTSP], ry[NPTSP], rq[NPTSP];
    __shared__ float red[4];
    __shared__ int s_last;
    int blk  = blockIdx.x;
    int b    = blk >> 3;
    int dir  = (blk >> 2) & 1;
    int part = blk & 3;
    int tid  = threadIdx.x;
    int qimg = dir ? (BATCH + b) : b;
    int rimg = dir ? b : (BATCH + b);
    int nq  = g_np[qimg];
    int nr8 = (g_np[rimg] + 7) & ~7;
    if (tid == 0) s_last = 0;
    for (int i = tid; i < nr8; i += 128) {
        rx[i] = g_lx[rimg * NPTSP + i];
        ry[i] = g_ly[rimg * NPTSP + i];
        rq[i] = g_q [rimg * NPTSP + i];
    }
    __syncthreads();
    int ch = (nq + PARTS - 1) / PARTS;       // <= 250
    int i0 = part * ch;
    int i1 = (i0 + ch < nq) ? (i0 + ch) : nq;
    int iqA = i0 + tid, iqB = i0 + tid + 128;
    bool actA = iqA < i1, actB = iqB < i1;
    int rdA = actA ? iqA : 0, rdB = actB ? iqB : 0;
    float xA = g_lx[qimg * NPTSP + rdA], yA = g_ly[qimg * NPTSP + rdA];
    float xB = g_lx[qimg * NPTSP + rdB], yB = g_ly[qimg * NPTSP + rdB];
    u64 nxA2 = pack2(-2.0f * xA), nyA2 = pack2(-2.0f * yA);
    u64 nxB2 = pack2(-2.0f * xB), nyB2 = pack2(-2.0f * yB);
    float xxA = fmaf(xA, xA, yA * yA);
    float xxB = fmaf(xB, xB, yB * yB);
    // 4 independent min-accumulator chains per query -> 1 dependent FMNMX/j-step
    float mA0 = 3.4e38f, mA1 = 3.4e38f, mA2 = 3.4e38f, mA3 = 3.4e38f;
    float mB0 = 3.4e38f, mB1 = 3.4e38f, mB2 = 3.4e38f, mB3 = 3.4e38f;
    for (int j = 0; j < nr8; j += 8) {
        const ulonglong2 tx0 = *reinterpret_cast<const ulonglong2*>(&rx[j]);
        const ulonglong2 ty0 = *reinterpret_cast<const ulonglong2*>(&ry[j]);
        const ulonglong2 tq0 = *reinterpret_cast<const ulonglong2*>(&rq[j]);
        const ulonglong2 tx1 = *reinterpret_cast<const ulonglong2*>(&rx[j + 4]);
        const ulonglong2 ty1 = *reinterpret_cast<const ulonglong2*>(&ry[j + 4]);
        const ulonglong2 tq1 = *reinterpret_cast<const ulonglong2*>(&rq[j + 4]);
        u64 i0v, i1v, i2v, i3v, d0, d1, d2, d3;
        // query A
        FMA2(i0v, ty0.x, nyA2, tq0.x);  FMA2(d0, tx0.x, nxA2, i0v);
        FMA2(i1v, ty0.y, nyA2, tq0.y);  FMA2(d1, tx0.y, nxA2, i1v);
        FMA2(i2v, ty1.x, nyA2, tq1.x);  FMA2(d2, tx1.x, nxA2, i2v);
        FMA2(i3v, ty1.y, nyA2, tq1.y);  FMA2(d3, tx1.y, nxA2, i3v);
        mA0 = fminf(mA0, fminf(lo2(d0), hi2(d0)));
        mA1 = fminf(mA1, fminf(lo2(d1), hi2(d1)));
        mA2 = fminf(mA2, fminf(lo2(d2), hi2(d2)));
        mA3 = fminf(mA3, fminf(lo2(d3), hi2(d3)));
        // query B
        FMA2(i0v, ty0.x, nyB2, tq0.x);  FMA2(d0, tx0.x, nxB2, i0v);
        FMA2(i1v, ty0.y, nyB2, tq0.y);  FMA2(d1, tx0.y, nxB2, i1v);
        FMA2(i2v, ty1.x, nyB2, tq1.x);  FMA2(d2, tx1.x, nxB2, i2v);
        FMA2(i3v, ty1.y, nyB2, tq1.y);  FMA2(d3, tx1.y, nxB2, i3v);
        mB0 = fminf(mB0, fminf(lo2(d0), hi2(d0)));
        mB1 = fminf(mB1, fminf(lo2(d1), hi2(d1)));
        mB2 = fminf(mB2, fminf(lo2(d2), hi2(d2)));
        mB3 = fminf(mB3, fminf(lo2(d3), hi2(d3)));
    }
    float lmax = 0.0f;
    if (actA) {
        float mA = fminf(fminf(mA0, mA1), fminf(mA2, mA3));
        lmax = fmaxf(lmax, fmaxf(mA + xxA, 0.0f));
    }
    if (actB) {
        float mB = fminf(fminf(mB0, mB1), fminf(mB2, mB3));
        lmax = fmaxf(lmax, fmaxf(mB + xxB, 0.0f));
    }
    for (int off = 16; off; off >>= 1)
        lmax = fmaxf(lmax, __shfl_down_sync(0xffffffffu, lmax, off));
    if ((tid & 31) == 0) red[tid >> 5] = lmax;
    __syncthreads();
    if (tid == 0) {
        float vv = fmaxf(fmaxf(red[0], red[1]), fmaxf(red[2], red[3]));
        atomicMax(&g_hdbits[b], __float_as_uint(vv));
        __threadfence();
        unsigned int old = atomicAdd(&g_done, 1u);
        s_last = (old == HDBLOCKS - 1);
    }
    __syncthreads();
    if (s_last && tid == 0) {
        __threadfence();
        float diag = sqrtf((float)(HDIM * HDIM + WDIM * WDIM));
        float ssum = 0.0f;
        for (int i = 0; i < BATCH; i++) {
            float hd = sqrtf(__uint_as_float(g_hdbits[i])) / diag;
            ssum += fminf(fmaxf(hd, 0.0f), 0.1f);
            g_hdbits[i] = 0u;                       // self-clean
        }
        out[0] = ssum / (float)BATCH;
        g_done = 0u;                                // self-clean
    }
}

// ---------------- launch ----------------
extern "C" void kernel_launch(void* const* d_in, const int* in_sizes, int n_in,
                              void* d_out, int out_size) {
    const float* pred   = (const float*)d_in[0];
    const float* target = (const float*)d_in[1];
    float* out = (float*)d_out;

    k_fused<<<NIMG * 64, 256>>>(pred, target);   // Sobel+RNG+accept+selection
    k_hd_mean<<<HDBLOCKS, 128>>>(out);           // Hausdorff + mean
}